// round 4
// baseline (speedup 1.0000x reference)
#include <cuda_runtime.h>
#include <cuda_bf16.h>
#include <cstdint>

// out[e*12 + 0..11] = W[h][rel_pos[e]]  -> gather of W^T rows.
// R4: 4-deep ring of 8KB staging buffers + cp.async.bulk stores (wait_group 3),
// 12 tiles per CTA. Same smem footprint as R3 (~35KB) but 2x outstanding-store
// depth and finer-grained drain waits.

#define THREADS       256
#define F4_PER_THREAD 2
#define TILE_F4       (THREADS * F4_PER_THREAD)   // 512 float4 = 8 KB
#define NBUF          4
#define TILES_PER_CTA 12                          // 96 KB contiguous per CTA

__device__ __forceinline__ unsigned smem_u32(const void* p) {
    unsigned a;
    asm("{ .reg .u64 x; cvta.to.shared.u64 x, %1; cvt.u32.u64 %0, x; }"
        : "=r"(a) : "l"(p));
    return a;
}

__global__ __launch_bounds__(THREADS)
void gather_wt_ring(const int* __restrict__ rel_pos,
                    const float* __restrict__ W,       // [12,64]
                    float4* __restrict__ out4)
{
    __shared__ __align__(16)  float4 table4[64 * 3];        // table4[cls*3+c]
    __shared__ __align__(128) float4 stage4[NBUF][TILE_F4]; // 4 x 8 KB

    float* table = reinterpret_cast<float*>(table4);
    unsigned t = threadIdx.x;

    // Transposed table: table[c*12 + h] = W[h*64 + c]
    #pragma unroll
    for (int i = 0; i < 3; i++) {
        unsigned j = t + i * 256u;           // [0,768)
        table[(j & 63u) * 12u + (j >> 6)] = W[j];
    }
    __syncthreads();

    unsigned tile0 = blockIdx.x * (unsigned)TILES_PER_CTA;

    #pragma unroll
    for (int it = 0; it < TILES_PER_CTA; it++) {
        int buf = it & (NBUF - 1);
        unsigned base = (tile0 + (unsigned)it) * (unsigned)TILE_F4;

        // Before reusing a ring slot, ensure its previous bulk store drained.
        if (it >= NBUF) {
            if (t == 0)
                asm volatile("cp.async.bulk.wait_group %0;" :: "n"(NBUF - 1) : "memory");
            __syncthreads();
        }

        // Gather: linear STS (conflict-free); random-row LDS from table.
        #pragma unroll
        for (int k = 0; k < F4_PER_THREAD; k++) {
            unsigned j = base + t + k * 256u;    // output float4 index
            unsigned e = j / 3u;                 // element
            unsigned c = j - e * 3u;             // chunk 0..2
            int cls = rel_pos[e];                // adjacent lanes merge in L1
            stage4[buf][t + k * 256u] = table4[(unsigned)cls * 3u + c];
        }
        __syncthreads();

        // Async bulk store: 8 KB smem -> gmem.
        if (t == 0) {
            unsigned saddr = smem_u32(stage4[buf]);
            unsigned long long gaddr = (unsigned long long)(out4 + base);
            asm volatile("fence.proxy.async;" ::: "memory");
            asm volatile("cp.async.bulk.global.shared::cta.bulk_group [%0], [%1], %2;"
                         :: "l"(gaddr), "r"(saddr), "n"(TILE_F4 * 16) : "memory");
            asm volatile("cp.async.bulk.commit_group;" ::: "memory");
        }
        // No sync after commit: buffer untouched until its wait above.
    }

    // Drain before CTA exit (smem handed to next CTA).
    if (t == 0)
        asm volatile("cp.async.bulk.wait_group 0;" ::: "memory");
    __syncthreads();
}

// Generic tail (unused for the benchmark shapes): direct gather + store.
__global__ __launch_bounds__(THREADS)
void gather_wt_tail(const int* __restrict__ rel_pos,
                    const float* __restrict__ W,
                    float4* __restrict__ out4,
                    unsigned start, unsigned n4)
{
    __shared__ float4 table4[64 * 3];
    float* table = reinterpret_cast<float*>(table4);
    unsigned t = threadIdx.x;
    #pragma unroll
    for (int i = 0; i < 3; i++) {
        unsigned j = t + i * 256u;
        table[(j & 63u) * 12u + (j >> 6)] = W[j];
    }
    __syncthreads();

    unsigned j = start + blockIdx.x * (unsigned)THREADS + t;
    if (j < n4) {
        unsigned e = j / 3u;
        unsigned c = j - e * 3u;
        int cls = rel_pos[e];
        out4[j] = table4[(unsigned)cls * 3u + c];
    }
}

extern "C" void kernel_launch(void* const* d_in, const int* in_sizes, int n_in,
                              void* d_out, int out_size)
{
    const int*   rel_pos = (const int*)d_in[0];    // [4,2048,2048] int32
    // d_in[1] = hidden_states (unused; dtype carrier only)
    const float* W       = (const float*)d_in[2];  // [12,64] float32
    float4*      out4    = (float4*)d_out;

    unsigned n_elem  = (unsigned)in_sizes[0];      // 16,777,216
    unsigned n4      = n_elem * 3u;                // 50,331,648 float4
    unsigned per_cta = (unsigned)(TILE_F4 * TILES_PER_CTA);   // 6144 float4
    unsigned blocks  = n4 / per_cta;               // 8192 exact for bench
    unsigned done    = blocks * per_cta;

    if (blocks)
        gather_wt_ring<<<blocks, THREADS>>>(rel_pos, W, out4);

    if (done < n4) {
        unsigned rem = n4 - done;
        unsigned tb  = (rem + THREADS - 1) / THREADS;
        gather_wt_tail<<<tb, THREADS>>>(rel_pos, W, out4, done, n4);
    }
}

// round 5
// speedup vs baseline: 1.0600x; 1.0600x over previous
#include <cuda_runtime.h>
#include <cuda_bf16.h>
#include <cstdint>

// out[e*12 + 0..11] = W[h][rel_pos[e]]  -> gather of W^T rows.
// R5: R3 double-buffer structure, but 32KB tiles / 512 threads: halves the
// per-byte TMA-op + sync overhead vs R3; warps/SM unchanged (3 CTA x 16 warps).

#define THREADS       512
#define F4_PER_THREAD 4
#define TILE_F4       (THREADS * F4_PER_THREAD)   // 2048 float4 = 32 KB
#define TILES_PER_CTA 8                           // 256 KB contiguous per CTA

__device__ __forceinline__ unsigned smem_u32(const void* p) {
    unsigned a;
    asm("{ .reg .u64 x; cvta.to.shared.u64 x, %1; cvt.u32.u64 %0, x; }"
        : "=r"(a) : "l"(p));
    return a;
}

__global__ __launch_bounds__(THREADS)
void gather_wt_pipe2(const int* __restrict__ rel_pos,
                     const float* __restrict__ W,       // [12,64]
                     float4* __restrict__ out4)
{
    __shared__ __align__(16)  float4 table4[64 * 3];        // table4[cls*3+c]
    __shared__ __align__(128) float4 stage4[2][TILE_F4];    // 2 x 32 KB

    float* table = reinterpret_cast<float*>(table4);
    unsigned t = threadIdx.x;

    // Transposed table: table[c*12 + h] = W[h*64 + c]
    #pragma unroll
    for (int i = 0; i < 2; i++) {
        unsigned j = t + i * (unsigned)THREADS;   // [0,1024)
        if (j < 768u)
            table[(j & 63u) * 12u + (j >> 6)] = W[j];
    }
    __syncthreads();

    unsigned tile0 = blockIdx.x * (unsigned)TILES_PER_CTA;

    #pragma unroll
    for (int it = 0; it < TILES_PER_CTA; it++) {
        int buf = it & 1;
        unsigned base = (tile0 + (unsigned)it) * (unsigned)TILE_F4;

        // Before reusing a buffer, ensure its previous bulk store drained.
        if (it >= 2) {
            if (t == 0)
                asm volatile("cp.async.bulk.wait_group 1;" ::: "memory");
            __syncthreads();
        }

        // Gather: linear STS (conflict-free); random-row LDS from table.
        #pragma unroll
        for (int k = 0; k < F4_PER_THREAD; k++) {
            unsigned j = base + t + k * (unsigned)THREADS;  // output float4 idx
            unsigned e = j / 3u;                            // element
            unsigned c = j - e * 3u;                        // chunk 0..2
            int cls = rel_pos[e];                           // lanes merge in L1
            stage4[buf][t + k * (unsigned)THREADS] = table4[(unsigned)cls * 3u + c];
        }
        __syncthreads();

        // Async bulk store: 32 KB smem -> gmem.
        if (t == 0) {
            unsigned saddr = smem_u32(stage4[buf]);
            unsigned long long gaddr = (unsigned long long)(out4 + base);
            asm volatile("fence.proxy.async;" ::: "memory");
            asm volatile("cp.async.bulk.global.shared::cta.bulk_group [%0], [%1], %2;"
                         :: "l"(gaddr), "r"(saddr), "n"(TILE_F4 * 16) : "memory");
            asm volatile("cp.async.bulk.commit_group;" ::: "memory");
        }
        // Buffer untouched until its wait above; no extra sync needed.
    }

    // Drain before CTA exit (smem handed to next CTA).
    if (t == 0)
        asm volatile("cp.async.bulk.wait_group 0;" ::: "memory");
    __syncthreads();
}

// Generic tail (unused for the benchmark shapes): direct gather + store.
__global__ __launch_bounds__(256)
void gather_wt_tail(const int* __restrict__ rel_pos,
                    const float* __restrict__ W,
                    float4* __restrict__ out4,
                    unsigned start, unsigned n4)
{
    __shared__ float4 table4[64 * 3];
    float* table = reinterpret_cast<float*>(table4);
    unsigned t = threadIdx.x;
    #pragma unroll
    for (int i = 0; i < 3; i++) {
        unsigned j = t + i * 256u;
        table[(j & 63u) * 12u + (j >> 6)] = W[j];
    }
    __syncthreads();

    unsigned j = start + blockIdx.x * 256u + t;
    if (j < n4) {
        unsigned e = j / 3u;
        unsigned c = j - e * 3u;
        int cls = rel_pos[e];
        out4[j] = table4[(unsigned)cls * 3u + c];
    }
}

extern "C" void kernel_launch(void* const* d_in, const int* in_sizes, int n_in,
                              void* d_out, int out_size)
{
    const int*   rel_pos = (const int*)d_in[0];    // [4,2048,2048] int32
    // d_in[1] = hidden_states (unused; dtype carrier only)
    const float* W       = (const float*)d_in[2];  // [12,64] float32
    float4*      out4    = (float4*)d_out;

    unsigned n_elem  = (unsigned)in_sizes[0];      // 16,777,216
    unsigned n4      = n_elem * 3u;                // 50,331,648 float4
    unsigned per_cta = (unsigned)(TILE_F4 * TILES_PER_CTA);   // 16384 float4
    unsigned blocks  = n4 / per_cta;               // 3072 exact for bench
    unsigned done    = blocks * per_cta;

    if (blocks)
        gather_wt_pipe2<<<blocks, THREADS>>>(rel_pos, W, out4);

    if (done < n4) {
        unsigned rem = n4 - done;
        unsigned tb  = (rem + 255u) / 256u;
        gather_wt_tail<<<tb, 256>>>(rel_pos, W, out4, done, n4);
    }
}